// round 7
// baseline (speedup 1.0000x reference)
#include <cuda_runtime.h>
#include <math.h>

#define Bq   2
#define Nn   2048
#define Dd   256
#define Hh   4
#define DHd  64
#define Jj   32
#define FFf  4
#define Mm   16
#define HID  274
#define HP   288            // padded hidden dim (cols 274..287 zero)
#define W2S  292            // sW2t row stride (floats)
#define QKVC (3*Hh*DHd)     // 768
#define NODES (Bq*Nn)       // 4096

// ---------------- scratch ----------------
__device__ float g_qkv [Bq*Nn*QKVC];
__device__ float g_q1  [Bq*Nn*Hh*HP];
__device__ float g_k1  [Bq*Nn*Hh*HP];
__device__ float g_sim [Bq*Hh*Nn*Jj];
__device__ float g_cw  [Bq*Hh*Nn*Jj];
__device__ float g_outh[Bq*Nn*Dd];

__global__ void noop_kernel() {}

// ---------------- generic 64x64 tiled SGEMM, C = A@B (+bias) ----------------
__global__ void gemm_tile(const float* __restrict__ A, const float* __restrict__ Bm,
                          const float* __restrict__ bias, float* __restrict__ C,
                          int M, int N, int K)
{
    __shared__ float As[16][65];
    __shared__ float Bs[16][65];
    int tid = threadIdx.x;
    int tx = tid & 15, ty = tid >> 4;
    int rowBase = blockIdx.y * 64;
    int colBase = blockIdx.x * 64;
    float acc[4][4] = {};
    for (int k0 = 0; k0 < K; k0 += 16) {
        for (int i = tid; i < 1024; i += 256) {
            int r = i >> 4, kk = i & 15;
            As[kk][r] = A[(long)(rowBase + r) * K + k0 + kk];
        }
        for (int i = tid; i < 1024; i += 256) {
            int kk = i >> 6, c = i & 63;
            Bs[kk][c] = Bm[(long)(k0 + kk) * N + colBase + c];
        }
        __syncthreads();
        #pragma unroll
        for (int kk = 0; kk < 16; kk++) {
            float a[4], bb[4];
            #pragma unroll
            for (int r = 0; r < 4; r++) a[r] = As[kk][ty*4 + r];
            #pragma unroll
            for (int c = 0; c < 4; c++) bb[c] = Bs[kk][tx*4 + c];
            #pragma unroll
            for (int r = 0; r < 4; r++)
                #pragma unroll
                for (int c = 0; c < 4; c++)
                    acc[r][c] += a[r] * bb[c];
        }
        __syncthreads();
    }
    #pragma unroll
    for (int r = 0; r < 4; r++) {
        int row = rowBase + ty*4 + r;
        #pragma unroll
        for (int c = 0; c < 4; c++) {
            int col = colBase + tx*4 + c;
            float v = acc[r][c];
            if (bias) v += bias[col];
            C[(long)row * N + col] = v;
        }
    }
}

// ---------------- q1/k1 precompute: row (node*4+h) = q_h(node) @ W1q ----------------
__global__ void __launch_bounds__(256,1) qk1_kernel(
    const float* __restrict__ qkv, const float* __restrict__ w_e1,
    float* __restrict__ q1, float* __restrict__ k1)
{
    extern __shared__ float sm[];
    float* sWq = sm;             // [64][HP]
    float* sWk = sWq + 64*HP;    // [64][HP]
    float* sAq = sWk + 64*HP;    // [16][256]
    float* sAk = sAq + 16*256;   // [16][256]
    int tid = threadIdx.x;
    int node0 = blockIdx.x * 16;

    for (int i = tid; i < 64*HP; i += 256) {
        int r = i / HP, o = i - r*HP;
        sWq[i] = (o < HID) ? w_e1[r*HID + o] : 0.f;
        sWk[i] = (o < HID) ? w_e1[(64 + r)*HID + o] : 0.f;
    }
    for (int i = tid; i < 4096; i += 256) {
        int t = i >> 8, c = i & 255;
        sAq[i] = qkv[(long)(node0 + t)*QKVC + c];
        sAk[i] = qkv[(long)(node0 + t)*QKVC + 256 + c];
    }
    __syncthreads();

    int ty = tid >> 4, tx = tid & 15;
    for (int pass = 0; pass < 2; pass++) {
        const float* A = pass ? sAk : sAq;
        const float* W = pass ? sWk : sWq;
        float* Cg = pass ? k1 : q1;
        float acc[4][18];
        #pragma unroll
        for (int r = 0; r < 4; r++)
            #pragma unroll
            for (int c = 0; c < 18; c++) acc[r][c] = 0.f;
        #pragma unroll 4
        for (int i = 0; i < 64; i++) {
            float a[4];
            #pragma unroll
            for (int r = 0; r < 4; r++) a[r] = A[ty*256 + r*64 + i];
            #pragma unroll
            for (int c = 0; c < 18; c++) {
                float w = W[i*HP + tx + 16*c];
                #pragma unroll
                for (int r = 0; r < 4; r++) acc[r][c] += a[r] * w;
            }
        }
        #pragma unroll
        for (int r = 0; r < 4; r++) {
            long grow = (long)(node0 + ty)*4 + r;
            #pragma unroll
            for (int c = 0; c < 18; c++)
                Cg[grow*HP + tx + 16*c] = acc[r][c];
        }
    }
}

// ---------------- edge_flat v3: warp = (node, j-pair); lane = (jj, hp, s) ----------------
// grid = NODES*2; block handles 16 j of one node. 2 heads per lane -> ~half regs.
__global__ void __launch_bounds__(256, 3) edge_flat(
    const float* __restrict__ q1, const float* __restrict__ k1,
    const float* __restrict__ coors, const int* __restrict__ nbhd,
    const float* __restrict__ w_e1, const float* __restrict__ b_e1,
    const float* __restrict__ w_e2, const float* __restrict__ b_e2,
    const float* __restrict__ w_a1, const float* __restrict__ b_a1,
    const float* __restrict__ w_a2, const float* __restrict__ b_a2,
    const float* __restrict__ w_c1, const float* __restrict__ b_c1,
    const float* __restrict__ w_c2, const float* __restrict__ b_c2,
    float* __restrict__ simo, float* __restrict__ cwo)
{
    extern __shared__ float sm[];
    float* sWr  = sm;               // [9][HP]
    float* sW2t = sWr + 9*HP;       // [16][W2S]  (transposed w_e2)
    float* sB1  = sW2t + 16*W2S;    // [HP]
    float* sQ1  = sB1 + HP;         // [4][HP]
    float* sA1  = sQ1 + 4*HP;       // [16][64]
    float* sC1  = sA1 + 1024;       // [16][64]
    float* sBa  = sC1 + 1024;       // [64]
    float* sBc  = sBa + 64;         // [64]
    float* sA2  = sBc + 64;         // [64]
    float* sC2  = sA2 + 64;         // [64]
    float* sB2  = sC2 + 64;         // [16]
    float* sScal= sB2 + 16;         // [4]
    int*   sIdx = (int*)(sScal + 4);// [16]

    int tid = threadIdx.x;
    int bn   = blockIdx.x >> 1;     // node
    int half = blockIdx.x & 1;
    int jbase = half * 16;
    int bB  = bn >> 11;
    int nn  = bn & (Nn - 1);

    for (int i = tid; i < 9*HP; i += 256) {
        int f = i / HP, o = i - f*HP;
        sWr[i] = (o < HID) ? w_e1[(128 + f)*HID + o] : 0.f;
    }
    for (int i = tid; i < 16*W2S; i += 256) {
        int t = i / W2S, o = i - t*W2S;
        sW2t[i] = (o < HID) ? w_e2[o*16 + t] : 0.f;
    }
    for (int i = tid; i < HP; i += 256) sB1[i] = (i < HID) ? b_e1[i] : 0.f;
    for (int i = tid; i < 4*HP; i += 256) sQ1[i] = q1[(long)bn*4*HP + i];
    for (int i = tid; i < 1024; i += 256) { sA1[i] = w_a1[i]; sC1[i] = w_c1[i]; }
    if (tid < 64) { sBa[tid] = b_a1[tid]; sBc[tid] = b_c1[tid];
                    sA2[tid] = w_a2[tid]; sC2[tid] = w_c2[tid]; }
    if (tid < 16) sB2[tid] = b_e2[tid];
    if (tid == 0) { sScal[0] = b_a2[0]; sScal[1] = b_c2[0]; }
    if (tid < 16) sIdx[tid] = nbhd[bn*Jj + jbase + tid];
    __syncthreads();

    int w = tid >> 5, lane = tid & 31;
    int jj = lane >> 4;              // 0/1 within warp
    int sub = lane & 15;
    int hp = sub >> 3;               // head pair: heads {2hp, 2hp+1}
    int s  = sub & 7;                // i-chunk lane
    int jl = w*2 + jj;               // local j (0..15)
    int j  = jbase + jl;             // global j
    int idx = sIdx[jl];
    long krow = ((long)(bB*Nn + idx)*4 + hp*2) * HP;
    const float* q1p = &sQ1[hp*2*HP];

    // rel_enc: lanes s=0..3 -> sin(x/2^s), s=4..7 -> cos(x/2^(s-4))
    float dx = coors[bn*3+0] - coors[(bB*Nn+idx)*3+0];
    float dy = coors[bn*3+1] - coors[(bB*Nn+idx)*3+1];
    float dz = coors[bn*3+2] - coors[(bB*Nn+idx)*3+2];
    float x = dx*dx + dy*dy + dz*dz;
    float xs = x / (float)(1 << (s & 3));
    float sv = sinf(xs), cv = cosf(xs);
    float myre = (s < 4) ? sv : cv;
    float re[9];
    #pragma unroll
    for (int f = 0; f < 8; f++) re[f] = __shfl_sync(0xffffffffu, myre, f, 8);
    re[8] = x;

    float acc[2][16];
    #pragma unroll
    for (int h = 0; h < 2; h++)
        #pragma unroll
        for (int t = 0; t < 16; t++) acc[h][t] = 0.f;

    #pragma unroll 3
    for (int r = 0; r < 9; r++) {
        int i0 = (s + 8*r) * 4;
        float4 k4a = *(const float4*)&k1[krow + i0];
        float4 k4b = *(const float4*)&k1[krow + HP + i0];
        // r1 chunk
        float4 r1v = *(float4*)&sB1[i0];
        #pragma unroll
        for (int f = 0; f < 9; f++) {
            float4 wv = *(float4*)&sWr[f*HP + i0];
            r1v.x += re[f]*wv.x; r1v.y += re[f]*wv.y;
            r1v.z += re[f]*wv.z; r1v.w += re[f]*wv.w;
        }
        float4 hv[2];
        {
            float4 q4 = *(const float4*)&q1p[i0];
            hv[0].x = fmaxf(q4.x + k4a.x + r1v.x, 0.f);
            hv[0].y = fmaxf(q4.y + k4a.y + r1v.y, 0.f);
            hv[0].z = fmaxf(q4.z + k4a.z + r1v.z, 0.f);
            hv[0].w = fmaxf(q4.w + k4a.w + r1v.w, 0.f);
            float4 q4b = *(const float4*)&q1p[HP + i0];
            hv[1].x = fmaxf(q4b.x + k4b.x + r1v.x, 0.f);
            hv[1].y = fmaxf(q4b.y + k4b.y + r1v.y, 0.f);
            hv[1].z = fmaxf(q4b.z + k4b.z + r1v.z, 0.f);
            hv[1].w = fmaxf(q4b.w + k4b.w + r1v.w, 0.f);
        }
        #pragma unroll
        for (int t = 0; t < 16; t++) {
            float4 wv = *(float4*)&sW2t[t*W2S + i0];
            acc[0][t] += hv[0].x*wv.x + hv[0].y*wv.y + hv[0].z*wv.z + hv[0].w*wv.w;
            acc[1][t] += hv[1].x*wv.x + hv[1].y*wv.y + hv[1].z*wv.z + hv[1].w*wv.w;
        }
    }

    // butterfly reduce over the 8-lane s-group
    #pragma unroll
    for (int h = 0; h < 2; h++)
        #pragma unroll
        for (int t = 0; t < 16; t++) {
            float v = acc[h][t];
            v += __shfl_xor_sync(0xffffffffu, v, 1);
            v += __shfl_xor_sync(0xffffffffu, v, 2);
            v += __shfl_xor_sync(0xffffffffu, v, 4);
            acc[h][t] = v;
        }

    // branch tasks: 8 lanes of s-group cover (hsel, br, u-half)
    int hsel = (s >> 2) & 1;         // head within pair
    int br   = (s >> 1) & 1;         // 0 = attention, 1 = coor
    int uh   = s & 1;                // u-half: 0 -> u[0:32), 1 -> u[32:64)
    int hh   = hp*2 + hsel;          // global head
    float mv[16];
    #pragma unroll
    for (int t = 0; t < 16; t++) {
        float v = hsel ? acc[1][t] : acc[0][t];
        mv[t] = fmaxf(v + sB2[t], 0.f);
    }
    const float* w1 = br ? sC1 : sA1;
    const float* w2 = br ? sC2 : sA2;
    const float* bb = br ? sBc : sBa;
    float bacc = 0.f;
    #pragma unroll 4
    for (int u4 = 0; u4 < 8; u4++) {
        int u0 = uh*32 + u4*4;
        float4 hv = *(float4*)&bb[u0];
        #pragma unroll
        for (int t = 0; t < 16; t++) {
            float4 wv = *(float4*)&w1[t*64 + u0];
            hv.x += mv[t]*wv.x; hv.y += mv[t]*wv.y;
            hv.z += mv[t]*wv.z; hv.w += mv[t]*wv.w;
        }
        float4 w2v = *(float4*)&w2[u0];
        bacc += fmaxf(hv.x,0.f)*w2v.x + fmaxf(hv.y,0.f)*w2v.y
              + fmaxf(hv.z,0.f)*w2v.z + fmaxf(hv.w,0.f)*w2v.w;
    }
    bacc += __shfl_xor_sync(0xffffffffu, bacc, 1);
    if (uh == 0) {
        long e = ((long)(bB*Hh + hh)*Nn + nn)*Jj + j;
        float val = bacc + (br ? sScal[1] : sScal[0]);
        (br ? cwo : simo)[e] = val;
    }
}

// ---------------- softmax over j, out = attn@v_nb, coors_out ----------------
__global__ void attend_kernel(const float* __restrict__ qkv,
                              const float* __restrict__ simi, const float* __restrict__ cwi,
                              const int* __restrict__ nbhd, const float* __restrict__ basis,
                              float* __restrict__ outh, float* __restrict__ coors_out)
{
    int bn = blockIdx.x;
    int b = bn / Nn, n = bn % Nn;
    int w = threadIdx.x >> 5, lane = threadIdx.x & 31;
    int idx = nbhd[bn*Jj + lane];

    float s = simi[((long)((b*Hh + w)*Nn + n))*Jj + lane];
    float mx = s;
    #pragma unroll
    for (int o = 16; o; o >>= 1) mx = fmaxf(mx, __shfl_xor_sync(0xffffffffu, mx, o));
    float e = expf(s - mx);
    float sum = e;
    #pragma unroll
    for (int o = 16; o; o >>= 1) sum += __shfl_xor_sync(0xffffffffu, sum, o);
    float attn = e / sum;

    float acc0 = 0.f, acc1 = 0.f;
    #pragma unroll
    for (int j = 0; j < Jj; j++) {
        float a = __shfl_sync(0xffffffffu, attn, j);
        int ij  = __shfl_sync(0xffffffffu, idx,  j);
        const float* vr = qkv + (long)(b*Nn + ij)*QKVC + 2*Hh*DHd + w*DHd;
        acc0 += a * vr[lane];
        acc1 += a * vr[lane + 32];
    }
    outh[(long)bn*Dd + w*DHd + lane]      = acc0;
    outh[(long)bn*Dd + w*DHd + lane + 32] = acc1;

    if (w == 0) {
        float cwt = 0.f;
        #pragma unroll
        for (int hh = 0; hh < Hh; hh++)
            cwt += cwi[((long)((b*Hh + hh)*Nn + n))*Jj + lane];
        const float* brow = basis + ((long)(b*Nn + n)*Nn + idx)*3;
        float cx = cwt*brow[0], cy = cwt*brow[1], cz = cwt*brow[2];
        #pragma unroll
        for (int o = 16; o; o >>= 1) {
            cx += __shfl_xor_sync(0xffffffffu, cx, o);
            cy += __shfl_xor_sync(0xffffffffu, cy, o);
            cz += __shfl_xor_sync(0xffffffffu, cz, o);
        }
        if (lane == 0) {
            coors_out[bn*3+0] = cx;
            coors_out[bn*3+1] = cy;
            coors_out[bn*3+2] = cz;
        }
    }
}

// ---------------- launch ----------------
extern "C" void kernel_launch(void* const* d_in, const int* in_sizes, int n_in,
                              void* d_out, int out_size)
{
    const float* feats  = (const float*)d_in[0];
    const float* coors  = (const float*)d_in[1];
    const float* basis  = (const float*)d_in[2];
    const int*   nbhd   = (const int*)  d_in[3];
    const float* w_qkv  = (const float*)d_in[4];
    const float* w_out  = (const float*)d_in[5];
    const float* b_out  = (const float*)d_in[6];
    const float* w_e1   = (const float*)d_in[7];
    const float* b_e1   = (const float*)d_in[8];
    const float* w_e2   = (const float*)d_in[9];
    const float* b_e2   = (const float*)d_in[10];
    const float* w_a1   = (const float*)d_in[11];
    const float* b_a1   = (const float*)d_in[12];
    const float* w_a2   = (const float*)d_in[13];
    const float* b_a2   = (const float*)d_in[14];
    const float* w_c1   = (const float*)d_in[15];
    const float* b_c1   = (const float*)d_in[16];
    const float* w_c2   = (const float*)d_in[17];
    const float* b_c2   = (const float*)d_in[18];

    float* out       = (float*)d_out;
    float* coors_out = out + (long)Bq*Nn*Dd;

    void* p;
    cudaGetSymbolAddress(&p, g_qkv);  float* qkv  = (float*)p;
    cudaGetSymbolAddress(&p, g_q1);   float* q1   = (float*)p;
    cudaGetSymbolAddress(&p, g_k1);   float* k1   = (float*)p;
    cudaGetSymbolAddress(&p, g_sim);  float* simv = (float*)p;
    cudaGetSymbolAddress(&p, g_cw);   float* cwv  = (float*)p;
    cudaGetSymbolAddress(&p, g_outh); float* outh = (float*)p;

    // 1) qkv = feats @ w_qkv
    gemm_tile<<<dim3(QKVC/64, (Bq*Nn)/64), 256>>>(feats, w_qkv, nullptr, qkv,
                                                  Bq*Nn, QKVC, Dd);

    // 2) q1/k1 tables
    const int smemQK = (64*HP*2 + 16*256*2) * 4;
    cudaFuncSetAttribute(qk1_kernel, cudaFuncAttributeMaxDynamicSharedMemorySize, smemQK);
    qk1_kernel<<<256, 256, smemQK>>>(qkv, w_e1, q1, k1);

    // 2.5) alignment no-op so the ncu -s 5 capture lands on edge_flat
    noop_kernel<<<1, 32>>>();

    // 3) edge_flat v3 (half-node blocks)
    const int smemE = (9*HP + 16*W2S + HP + 4*HP + 1024 + 1024 + 64*4 + 16 + 4 + 16) * 4;
    cudaFuncSetAttribute(edge_flat, cudaFuncAttributeMaxDynamicSharedMemorySize, smemE);
    edge_flat<<<NODES*2, 256, smemE>>>(q1, k1, coors, nbhd,
        w_e1, b_e1, w_e2, b_e2, w_a1, b_a1, w_a2, b_a2, w_c1, b_c1, w_c2, b_c2,
        simv, cwv);

    // 4) softmax + v-gather + coors einsum
    attend_kernel<<<Bq*Nn, 128>>>(qkv, simv, cwv, nbhd, basis, outh, coors_out);

    // 5) out = outh @ w_out + b_out
    gemm_tile<<<dim3(Dd/64, (Bq*Nn)/64), 256>>>(outh, w_out, b_out, out,
                                                Bq*Nn, Dd, Dd);
}

// round 8
// speedup vs baseline: 2.0214x; 2.0214x over previous
#include <cuda_runtime.h>
#include <math.h>

#define Bq   2
#define Nn   2048
#define Dd   256
#define Hh   4
#define DHd  64
#define Jj   32
#define FFf  4
#define Mm   16
#define HID  274
#define HP   288            // padded hidden dim (cols 274..287 zero)
#define W2S  292            // sW2t row stride (floats)
#define QKVC (3*Hh*DHd)     // 768
#define NODES (Bq*Nn)       // 4096

// ---------------- scratch ----------------
__device__ float g_qkv [Bq*Nn*QKVC];
__device__ float g_q1  [Bq*Nn*Hh*HP];
__device__ float g_k1  [Bq*Nn*Hh*HP];
__device__ float g_sim [Bq*Hh*Nn*Jj];
__device__ float g_cw  [Bq*Hh*Nn*Jj];
__device__ float g_outh[Bq*Nn*Dd];

__global__ void noop_kernel() {}

// ---------------- generic 64x64 tiled SGEMM, C = A@B (+bias) ----------------
__global__ void gemm_tile(const float* __restrict__ A, const float* __restrict__ Bm,
                          const float* __restrict__ bias, float* __restrict__ C,
                          int M, int N, int K)
{
    __shared__ float As[16][65];
    __shared__ float Bs[16][65];
    int tid = threadIdx.x;
    int tx = tid & 15, ty = tid >> 4;
    int rowBase = blockIdx.y * 64;
    int colBase = blockIdx.x * 64;
    float acc[4][4] = {};
    for (int k0 = 0; k0 < K; k0 += 16) {
        for (int i = tid; i < 1024; i += 256) {
            int r = i >> 4, kk = i & 15;
            As[kk][r] = A[(long)(rowBase + r) * K + k0 + kk];
        }
        for (int i = tid; i < 1024; i += 256) {
            int kk = i >> 6, c = i & 63;
            Bs[kk][c] = Bm[(long)(k0 + kk) * N + colBase + c];
        }
        __syncthreads();
        #pragma unroll
        for (int kk = 0; kk < 16; kk++) {
            float a[4], bb[4];
            #pragma unroll
            for (int r = 0; r < 4; r++) a[r] = As[kk][ty*4 + r];
            #pragma unroll
            for (int c = 0; c < 4; c++) bb[c] = Bs[kk][tx*4 + c];
            #pragma unroll
            for (int r = 0; r < 4; r++)
                #pragma unroll
                for (int c = 0; c < 4; c++)
                    acc[r][c] += a[r] * bb[c];
        }
        __syncthreads();
    }
    #pragma unroll
    for (int r = 0; r < 4; r++) {
        int row = rowBase + ty*4 + r;
        #pragma unroll
        for (int c = 0; c < 4; c++) {
            int col = colBase + tx*4 + c;
            float v = acc[r][c];
            if (bias) v += bias[col];
            C[(long)row * N + col] = v;
        }
    }
}

// ---------------- q1/k1 precompute; b_e1 folded into q1 ----------------
__global__ void __launch_bounds__(256,1) qk1_kernel(
    const float* __restrict__ qkv, const float* __restrict__ w_e1,
    const float* __restrict__ b_e1,
    float* __restrict__ q1, float* __restrict__ k1)
{
    extern __shared__ float sm[];
    float* sWq = sm;             // [64][HP]
    float* sWk = sWq + 64*HP;    // [64][HP]
    float* sAq = sWk + 64*HP;    // [16][256]
    float* sAk = sAq + 16*256;   // [16][256]
    int tid = threadIdx.x;
    int node0 = blockIdx.x * 16;

    for (int i = tid; i < 64*HP; i += 256) {
        int r = i / HP, o = i - r*HP;
        sWq[i] = (o < HID) ? w_e1[r*HID + o] : 0.f;
        sWk[i] = (o < HID) ? w_e1[(64 + r)*HID + o] : 0.f;
    }
    for (int i = tid; i < 4096; i += 256) {
        int t = i >> 8, c = i & 255;
        sAq[i] = qkv[(long)(node0 + t)*QKVC + c];
        sAk[i] = qkv[(long)(node0 + t)*QKVC + 256 + c];
    }
    __syncthreads();

    int ty = tid >> 4, tx = tid & 15;
    for (int pass = 0; pass < 2; pass++) {
        const float* A = pass ? sAk : sAq;
        const float* W = pass ? sWk : sWq;
        float* Cg = pass ? k1 : q1;
        float acc[4][18];
        #pragma unroll
        for (int r = 0; r < 4; r++)
            #pragma unroll
            for (int c = 0; c < 18; c++) acc[r][c] = 0.f;
        #pragma unroll 4
        for (int i = 0; i < 64; i++) {
            float a[4];
            #pragma unroll
            for (int r = 0; r < 4; r++) a[r] = A[ty*256 + r*64 + i];
            #pragma unroll
            for (int c = 0; c < 18; c++) {
                float w = W[i*HP + tx + 16*c];
                #pragma unroll
                for (int r = 0; r < 4; r++) acc[r][c] += a[r] * w;
            }
        }
        #pragma unroll
        for (int r = 0; r < 4; r++) {
            long grow = (long)(node0 + ty)*4 + r;
            #pragma unroll
            for (int c = 0; c < 18; c++) {
                int o = tx + 16*c;
                float bz = (pass == 0 && o < HID) ? b_e1[o] : 0.f;
                Cg[grow*HP + o] = acc[r][c] + bz;
            }
        }
    }
}

// ---------------- edge_flat (round-6 v2): warp = (node, j-quad), 4 heads/lane ----------------
__global__ void __launch_bounds__(256, 2) edge_flat(
    const float* __restrict__ q1, const float* __restrict__ k1,
    const float* __restrict__ coors, const int* __restrict__ nbhd,
    const float* __restrict__ w_e1,
    const float* __restrict__ w_e2, const float* __restrict__ b_e2,
    const float* __restrict__ w_a1, const float* __restrict__ b_a1,
    const float* __restrict__ w_a2, const float* __restrict__ b_a2,
    const float* __restrict__ w_c1, const float* __restrict__ b_c1,
    const float* __restrict__ w_c2, const float* __restrict__ b_c2,
    float* __restrict__ simo, float* __restrict__ cwo)
{
    extern __shared__ float sm[];
    float* sWr  = sm;               // [9][HP]
    float* sW2t = sWr + 9*HP;       // [16][W2S]  (transposed w_e2)
    float* sQ1  = sW2t + 16*W2S;    // [4][HP]  (q1 row incl. b1)
    float* sA1  = sQ1 + 4*HP;       // [16][64]
    float* sC1  = sA1 + 1024;       // [16][64]
    float* sBa  = sC1 + 1024;       // [64]
    float* sBc  = sBa + 64;         // [64]
    float* sA2  = sBc + 64;         // [64]
    float* sC2  = sA2 + 64;         // [64]
    float* sB2  = sC2 + 64;         // [16]
    float* sScal= sB2 + 16;         // [4]
    int*   sIdx = (int*)(sScal + 4);// [32]

    int tid = threadIdx.x;
    int bn  = blockIdx.x;
    int bB  = bn >> 11;
    int nn  = bn & (Nn - 1);

    // sWr scalar staging (rows 8-byte aligned only; zero-pads cols >= HID)
    for (int i = tid; i < 9*HP; i += 256) {
        int f = i / HP, o = i - f*HP;
        sWr[i] = (o < HID) ? w_e1[(128 + f)*HID + o] : 0.f;
    }
    // sW2t: zero tail cols [HID, W2S), then vectorized transpose fill
    for (int i = tid; i < 16*(W2S - HID); i += 256) {
        int t = i / (W2S - HID), o = HID + i % (W2S - HID);
        sW2t[t*W2S + o] = 0.f;
    }
    for (int i = tid; i < HID*4; i += 256) {          // i-row, t-quad
        int irow = i >> 2, tq = i & 3;
        float4 v = *(const float4*)&w_e2[irow*16 + tq*4];
        sW2t[(tq*4+0)*W2S + irow] = v.x;
        sW2t[(tq*4+1)*W2S + irow] = v.y;
        sW2t[(tq*4+2)*W2S + irow] = v.z;
        sW2t[(tq*4+3)*W2S + irow] = v.w;
    }
    // sQ1 float4 staging (q1 already includes b1)
    for (int i = tid; i < (4*HP)/4; i += 256)
        ((float4*)sQ1)[i] = ((const float4*)(q1 + (long)bn*4*HP))[i];
    // branch weights float4
    if (tid < 256) {
        ((float4*)sA1)[tid] = ((const float4*)w_a1)[tid];
        ((float4*)sC1)[tid] = ((const float4*)w_c1)[tid];
    }
    if (tid < 16) {
        ((float4*)sBa)[tid] = ((const float4*)b_a1)[tid];
        ((float4*)sBc)[tid] = ((const float4*)b_c1)[tid];
        ((float4*)sA2)[tid] = ((const float4*)w_a2)[tid];
        ((float4*)sC2)[tid] = ((const float4*)w_c2)[tid];
    }
    if (tid < 16) sB2[tid] = b_e2[tid];
    if (tid == 0) { sScal[0] = b_a2[0]; sScal[1] = b_c2[0]; }
    if (tid < 32) sIdx[tid] = nbhd[bn*Jj + tid];
    __syncthreads();

    int w = tid >> 5, lane = tid & 31;
    int qq = lane >> 3, s = lane & 7;
    int j = w*4 + qq;
    int idx = sIdx[j];
    long krow = ((long)(bB*Nn + idx)*4) * HP;

    // rel_enc: lanes s=0..3 -> sin(x/2^s), s=4..7 -> cos(x/2^(s-4))
    float dx = coors[bn*3+0] - coors[(bB*Nn+idx)*3+0];
    float dy = coors[bn*3+1] - coors[(bB*Nn+idx)*3+1];
    float dz = coors[bn*3+2] - coors[(bB*Nn+idx)*3+2];
    float x = dx*dx + dy*dy + dz*dz;
    float xs = x / (float)(1 << (s & 3));
    float sv = sinf(xs), cv = cosf(xs);
    float myre = (s < 4) ? sv : cv;
    float re[9];
    #pragma unroll
    for (int f = 0; f < 8; f++) re[f] = __shfl_sync(0xffffffffu, myre, f, 8);
    re[8] = x;

    float acc[4][16];
    #pragma unroll
    for (int h = 0; h < 4; h++)
        #pragma unroll
        for (int t = 0; t < 16; t++) acc[h][t] = 0.f;

    #pragma unroll 3
    for (int r = 0; r < 9; r++) {
        int i0 = (s + 8*r) * 4;
        // k1 global loads issued first
        float4 k4[4];
        #pragma unroll
        for (int h = 0; h < 4; h++)
            k4[h] = *(const float4*)&k1[krow + h*HP + i0];
        // r1 chunk (b1 folded into q1; start from zero)
        float4 r1v = make_float4(0.f, 0.f, 0.f, 0.f);
        #pragma unroll
        for (int f = 0; f < 9; f++) {
            float4 wv = *(float4*)&sWr[f*HP + i0];
            r1v.x += re[f]*wv.x; r1v.y += re[f]*wv.y;
            r1v.z += re[f]*wv.z; r1v.w += re[f]*wv.w;
        }
        // h chunks, 4 heads
        float4 hv[4];
        #pragma unroll
        for (int h = 0; h < 4; h++) {
            float4 q4 = *(float4*)&sQ1[h*HP + i0];
            hv[h].x = fmaxf(q4.x + k4[h].x + r1v.x, 0.f);
            hv[h].y = fmaxf(q4.y + k4[h].y + r1v.y, 0.f);
            hv[h].z = fmaxf(q4.z + k4[h].z + r1v.z, 0.f);
            hv[h].w = fmaxf(q4.w + k4[h].w + r1v.w, 0.f);
        }
        // layer2: W2 row chunk loaded once, used by all 4 heads
        #pragma unroll
        for (int t = 0; t < 16; t++) {
            float4 wv = *(float4*)&sW2t[t*W2S + i0];
            #pragma unroll
            for (int h = 0; h < 4; h++)
                acc[h][t] += hv[h].x*wv.x + hv[h].y*wv.y
                           + hv[h].z*wv.z + hv[h].w*wv.w;
        }
    }

    // butterfly reduce over 8-lane group
    #pragma unroll
    for (int h = 0; h < 4; h++)
        #pragma unroll
        for (int t = 0; t < 16; t++) {
            float v = acc[h][t];
            v += __shfl_xor_sync(0xffffffffu, v, 1);
            v += __shfl_xor_sync(0xffffffffu, v, 2);
            v += __shfl_xor_sync(0xffffffffu, v, 4);
            acc[h][t] = v;
        }

    // branch task per lane: h = s>>1, br = s&1
    int hh = s >> 1, br = s & 1;
    float mv[16];
    #pragma unroll
    for (int t = 0; t < 16; t++) {
        float v01 = (hh & 1) ? acc[1][t] : acc[0][t];
        float v23 = (hh & 1) ? acc[3][t] : acc[2][t];
        float v = (hh & 2) ? v23 : v01;
        mv[t] = fmaxf(v + sB2[t], 0.f);
    }
    const float* w1 = br ? sC1 : sA1;
    const float* w2 = br ? sC2 : sA2;
    const float* bb = br ? sBc : sBa;
    float bacc = 0.f;
    #pragma unroll 4
    for (int u4 = 0; u4 < 16; u4++) {
        float4 hv = *(float4*)&bb[u4*4];
        #pragma unroll
        for (int t = 0; t < 16; t++) {
            float4 wv = *(float4*)&w1[t*64 + u4*4];
            hv.x += mv[t]*wv.x; hv.y += mv[t]*wv.y;
            hv.z += mv[t]*wv.z; hv.w += mv[t]*wv.w;
        }
        float4 w2v = *(float4*)&w2[u4*4];
        bacc += fmaxf(hv.x,0.f)*w2v.x + fmaxf(hv.y,0.f)*w2v.y
              + fmaxf(hv.z,0.f)*w2v.z + fmaxf(hv.w,0.f)*w2v.w;
    }
    long e = ((long)(bB*Hh + hh)*Nn + nn)*Jj + j;
    float val = bacc + (br ? sScal[1] : sScal[0]);
    (br ? cwo : simo)[e] = val;
}

// ---------------- softmax over j, out = attn@v_nb, coors_out ----------------
__global__ void attend_kernel(const float* __restrict__ qkv,
                              const float* __restrict__ simi, const float* __restrict__ cwi,
                              const int* __restrict__ nbhd, const float* __restrict__ basis,
                              float* __restrict__ outh, float* __restrict__ coors_out)
{
    int bn = blockIdx.x;
    int b = bn / Nn, n = bn % Nn;
    int w = threadIdx.x >> 5, lane = threadIdx.x & 31;
    int idx = nbhd[bn*Jj + lane];

    float s = simi[((long)((b*Hh + w)*Nn + n))*Jj + lane];
    float mx = s;
    #pragma unroll
    for (int o = 16; o; o >>= 1) mx = fmaxf(mx, __shfl_xor_sync(0xffffffffu, mx, o));
    float e = expf(s - mx);
    float sum = e;
    #pragma unroll
    for (int o = 16; o; o >>= 1) sum += __shfl_xor_sync(0xffffffffu, sum, o);
    float attn = e / sum;

    float acc0 = 0.f, acc1 = 0.f;
    #pragma unroll
    for (int j = 0; j < Jj; j++) {
        float a = __shfl_sync(0xffffffffu, attn, j);
        int ij  = __shfl_sync(0xffffffffu, idx,  j);
        const float* vr = qkv + (long)(b*Nn + ij)*QKVC + 2*Hh*DHd + w*DHd;
        acc0 += a * vr[lane];
        acc1 += a * vr[lane + 32];
    }
    outh[(long)bn*Dd + w*DHd + lane]      = acc0;
    outh[(long)bn*Dd + w*DHd + lane + 32] = acc1;

    if (w == 0) {
        float cwt = 0.f;
        #pragma unroll
        for (int hh = 0; hh < Hh; hh++)
            cwt += cwi[((long)((b*Hh + hh)*Nn + n))*Jj + lane];
        const float* brow = basis + ((long)(b*Nn + n)*Nn + idx)*3;
        float cx = cwt*brow[0], cy = cwt*brow[1], cz = cwt*brow[2];
        #pragma unroll
        for (int o = 16; o; o >>= 1) {
            cx += __shfl_xor_sync(0xffffffffu, cx, o);
            cy += __shfl_xor_sync(0xffffffffu, cy, o);
            cz += __shfl_xor_sync(0xffffffffu, cz, o);
        }
        if (lane == 0) {
            coors_out[bn*3+0] = cx;
            coors_out[bn*3+1] = cy;
            coors_out[bn*3+2] = cz;
        }
    }
}

// ---------------- launch ----------------
extern "C" void kernel_launch(void* const* d_in, const int* in_sizes, int n_in,
                              void* d_out, int out_size)
{
    const float* feats  = (const float*)d_in[0];
    const float* coors  = (const float*)d_in[1];
    const float* basis  = (const float*)d_in[2];
    const int*   nbhd   = (const int*)  d_in[3];
    const float* w_qkv  = (const float*)d_in[4];
    const float* w_out  = (const float*)d_in[5];
    const float* b_out  = (const float*)d_in[6];
    const float* w_e1   = (const float*)d_in[7];
    const float* b_e1   = (const float*)d_in[8];
    const float* w_e2   = (const float*)d_in[9];
    const float* b_e2   = (const float*)d_in[10];
    const float* w_a1   = (const float*)d_in[11];
    const float* b_a1   = (const float*)d_in[12];
    const float* w_a2   = (const float*)d_in[13];
    const float* b_a2   = (const float*)d_in[14];
    const float* w_c1   = (const float*)d_in[15];
    const float* b_c1   = (const float*)d_in[16];
    const float* w_c2   = (const float*)d_in[17];
    const float* b_c2   = (const float*)d_in[18];

    float* out       = (float*)d_out;
    float* coors_out = out + (long)Bq*Nn*Dd;

    void* p;
    cudaGetSymbolAddress(&p, g_qkv);  float* qkv  = (float*)p;
    cudaGetSymbolAddress(&p, g_q1);   float* q1   = (float*)p;
    cudaGetSymbolAddress(&p, g_k1);   float* k1   = (float*)p;
    cudaGetSymbolAddress(&p, g_sim);  float* simv = (float*)p;
    cudaGetSymbolAddress(&p, g_cw);   float* cwv  = (float*)p;
    cudaGetSymbolAddress(&p, g_outh); float* outh = (float*)p;

    // 1) qkv = feats @ w_qkv
    gemm_tile<<<dim3(QKVC/64, (Bq*Nn)/64), 256>>>(feats, w_qkv, nullptr, qkv,
                                                  Bq*Nn, QKVC, Dd);

    // 2) q1/k1 tables (b_e1 folded into q1)
    const int smemQK = (64*HP*2 + 16*256*2) * 4;
    cudaFuncSetAttribute(qk1_kernel, cudaFuncAttributeMaxDynamicSharedMemorySize, smemQK);
    qk1_kernel<<<256, 256, smemQK>>>(qkv, w_e1, b_e1, q1, k1);

    // 2.5) alignment no-op so the ncu capture lands on edge_flat
    noop_kernel<<<1, 32>>>();

    // 3) edge_flat v2
    const int smemE = (9*HP + 16*W2S + 4*HP + 1024 + 1024 + 64*4 + 16 + 4 + 32) * 4;
    cudaFuncSetAttribute(edge_flat, cudaFuncAttributeMaxDynamicSharedMemorySize, smemE);
    edge_flat<<<NODES, 256, smemE>>>(q1, k1, coors, nbhd,
        w_e1, w_e2, b_e2, w_a1, b_a1, w_a2, b_a2, w_c1, b_c1, w_c2, b_c2,
        simv, cwv);

    // 4) softmax + v-gather + coors einsum
    attend_kernel<<<Bq*Nn, 128>>>(qkv, simv, cwv, nbhd, basis, outh, coors_out);

    // 5) out = outh @ w_out + b_out
    gemm_tile<<<dim3(Dd/64, (Bq*Nn)/64), 256>>>(outh, w_out, b_out, out,
                                                Bq*Nn, Dd, Dd);
}

// round 9
// speedup vs baseline: 2.1101x; 1.0439x over previous
#include <cuda_runtime.h>
#include <math.h>

#define Bq   2
#define Nn   2048
#define Dd   256
#define Hh   4
#define DHd  64
#define Jj   32
#define FFf  4
#define Mm   16
#define HID  274
#define HP   288            // padded hidden dim (cols 274..287 zero)
#define W2S  292            // sW2t row stride (floats)
#define QKVC (3*Hh*DHd)     // 768
#define NODES (Bq*Nn)       // 4096

// ---------------- scratch ----------------
__device__ float g_qkv [Bq*Nn*QKVC];
__device__ float g_q1  [Bq*Nn*Hh*HP];
__device__ float g_k1  [Bq*Nn*Hh*HP];
__device__ float g_sim [Bq*Hh*Nn*Jj];
__device__ float g_cw  [Bq*Hh*Nn*Jj];
__device__ float g_outh[Bq*Nn*Dd];

__global__ void noop_kernel() {}

// ---------------- generic 64x64 tiled SGEMM, C = A@B (+bias) ----------------
__global__ void gemm_tile(const float* __restrict__ A, const float* __restrict__ Bm,
                          const float* __restrict__ bias, float* __restrict__ C,
                          int M, int N, int K)
{
    __shared__ float As[16][65];
    __shared__ float Bs[16][65];
    int tid = threadIdx.x;
    int tx = tid & 15, ty = tid >> 4;
    int rowBase = blockIdx.y * 64;
    int colBase = blockIdx.x * 64;
    float acc[4][4] = {};
    for (int k0 = 0; k0 < K; k0 += 16) {
        for (int i = tid; i < 1024; i += 256) {
            int r = i >> 4, kk = i & 15;
            As[kk][r] = A[(long)(rowBase + r) * K + k0 + kk];
        }
        for (int i = tid; i < 1024; i += 256) {
            int kk = i >> 6, c = i & 63;
            Bs[kk][c] = Bm[(long)(k0 + kk) * N + colBase + c];
        }
        __syncthreads();
        #pragma unroll
        for (int kk = 0; kk < 16; kk++) {
            float a[4], bb[4];
            #pragma unroll
            for (int r = 0; r < 4; r++) a[r] = As[kk][ty*4 + r];
            #pragma unroll
            for (int c = 0; c < 4; c++) bb[c] = Bs[kk][tx*4 + c];
            #pragma unroll
            for (int r = 0; r < 4; r++)
                #pragma unroll
                for (int c = 0; c < 4; c++)
                    acc[r][c] += a[r] * bb[c];
        }
        __syncthreads();
    }
    #pragma unroll
    for (int r = 0; r < 4; r++) {
        int row = rowBase + ty*4 + r;
        #pragma unroll
        for (int c = 0; c < 4; c++) {
            int col = colBase + tx*4 + c;
            float v = acc[r][c];
            if (bias) v += bias[col];
            C[(long)row * N + col] = v;
        }
    }
}

// ---------------- q1/k1 precompute; b_e1 folded into q1 ----------------
__global__ void __launch_bounds__(256,1) qk1_kernel(
    const float* __restrict__ qkv, const float* __restrict__ w_e1,
    const float* __restrict__ b_e1,
    float* __restrict__ q1, float* __restrict__ k1)
{
    extern __shared__ float sm[];
    float* sWq = sm;             // [64][HP]
    float* sWk = sWq + 64*HP;    // [64][HP]
    float* sAq = sWk + 64*HP;    // [16][256]
    float* sAk = sAq + 16*256;   // [16][256]
    int tid = threadIdx.x;
    int node0 = blockIdx.x * 16;

    for (int i = tid; i < 64*HP; i += 256) {
        int r = i / HP, o = i - r*HP;
        sWq[i] = (o < HID) ? w_e1[r*HID + o] : 0.f;
        sWk[i] = (o < HID) ? w_e1[(64 + r)*HID + o] : 0.f;
    }
    for (int i = tid; i < 4096; i += 256) {
        int t = i >> 8, c = i & 255;
        sAq[i] = qkv[(long)(node0 + t)*QKVC + c];
        sAk[i] = qkv[(long)(node0 + t)*QKVC + 256 + c];
    }
    __syncthreads();

    int ty = tid >> 4, tx = tid & 15;
    for (int pass = 0; pass < 2; pass++) {
        const float* A = pass ? sAk : sAq;
        const float* W = pass ? sWk : sWq;
        float* Cg = pass ? k1 : q1;
        float acc[4][18];
        #pragma unroll
        for (int r = 0; r < 4; r++)
            #pragma unroll
            for (int c = 0; c < 18; c++) acc[r][c] = 0.f;
        #pragma unroll 4
        for (int i = 0; i < 64; i++) {
            float a[4];
            #pragma unroll
            for (int r = 0; r < 4; r++) a[r] = A[ty*256 + r*64 + i];
            #pragma unroll
            for (int c = 0; c < 18; c++) {
                float w = W[i*HP + tx + 16*c];
                #pragma unroll
                for (int r = 0; r < 4; r++) acc[r][c] += a[r] * w;
            }
        }
        #pragma unroll
        for (int r = 0; r < 4; r++) {
            long grow = (long)(node0 + ty)*4 + r;
            #pragma unroll
            for (int c = 0; c < 18; c++) {
                int o = tx + 16*c;
                float bz = (pass == 0 && o < HID) ? b_e1[o] : 0.f;
                Cg[grow*HP + o] = acc[r][c] + bz;
            }
        }
    }
}

// ---------------- edge_flat v4: v2 main loop + smem-m blocked branch GEMM ----------------
__global__ void __launch_bounds__(256, 2) edge_flat(
    const float* __restrict__ q1, const float* __restrict__ k1,
    const float* __restrict__ coors, const int* __restrict__ nbhd,
    const float* __restrict__ w_e1,
    const float* __restrict__ w_e2, const float* __restrict__ b_e2,
    const float* __restrict__ w_a1, const float* __restrict__ b_a1,
    const float* __restrict__ w_a2, const float* __restrict__ b_a2,
    const float* __restrict__ w_c1, const float* __restrict__ b_c1,
    const float* __restrict__ w_c2, const float* __restrict__ b_c2,
    float* __restrict__ simo, float* __restrict__ cwo)
{
    extern __shared__ float sm[];
    float* sWr  = sm;               // [9][HP]
    float* sW2t = sWr + 9*HP;       // [16][W2S]  (transposed w_e2)
    float* sQ1  = sW2t + 16*W2S;    // [4][HP]  (q1 row incl. b1)
    float* sA1  = sQ1 + 4*HP;       // [16][64]
    float* sC1  = sA1 + 1024;       // [16][64]
    float* sBa  = sC1 + 1024;       // [64]
    float* sBc  = sBa + 64;         // [64]
    float* sA2  = sBc + 64;         // [64]
    float* sC2  = sA2 + 64;         // [64]
    float* sB2  = sC2 + 64;         // [16]
    float* sScal= sB2 + 16;         // [4]
    int*   sIdx = (int*)(sScal + 4);// [32]
    float* sM   = (float*)(sIdx + 32); // [128][16]  m values (row = j*4+h)

    int tid = threadIdx.x;
    int bn  = blockIdx.x;
    int bB  = bn >> 11;
    int nn  = bn & (Nn - 1);

    for (int i = tid; i < 9*HP; i += 256) {
        int f = i / HP, o = i - f*HP;
        sWr[i] = (o < HID) ? w_e1[(128 + f)*HID + o] : 0.f;
    }
    for (int i = tid; i < 16*(W2S - HID); i += 256) {
        int t = i / (W2S - HID), o = HID + i % (W2S - HID);
        sW2t[t*W2S + o] = 0.f;
    }
    for (int i = tid; i < HID*4; i += 256) {          // i-row, t-quad
        int irow = i >> 2, tq = i & 3;
        float4 v = *(const float4*)&w_e2[irow*16 + tq*4];
        sW2t[(tq*4+0)*W2S + irow] = v.x;
        sW2t[(tq*4+1)*W2S + irow] = v.y;
        sW2t[(tq*4+2)*W2S + irow] = v.z;
        sW2t[(tq*4+3)*W2S + irow] = v.w;
    }
    for (int i = tid; i < (4*HP)/4; i += 256)
        ((float4*)sQ1)[i] = ((const float4*)(q1 + (long)bn*4*HP))[i];
    if (tid < 256) {
        ((float4*)sA1)[tid] = ((const float4*)w_a1)[tid];
        ((float4*)sC1)[tid] = ((const float4*)w_c1)[tid];
    }
    if (tid < 16) {
        ((float4*)sBa)[tid] = ((const float4*)b_a1)[tid];
        ((float4*)sBc)[tid] = ((const float4*)b_c1)[tid];
        ((float4*)sA2)[tid] = ((const float4*)w_a2)[tid];
        ((float4*)sC2)[tid] = ((const float4*)w_c2)[tid];
    }
    if (tid < 16) sB2[tid] = b_e2[tid];
    if (tid == 0) { sScal[0] = b_a2[0]; sScal[1] = b_c2[0]; }
    if (tid < 32) sIdx[tid] = nbhd[bn*Jj + tid];
    __syncthreads();

    int w = tid >> 5, lane = tid & 31;
    int qq = lane >> 3, s = lane & 7;
    int j = w*4 + qq;
    int idx = sIdx[j];
    long krow = ((long)(bB*Nn + idx)*4) * HP;

    // rel_enc: lanes s=0..3 -> sin(x/2^s), s=4..7 -> cos(x/2^(s-4))
    float dx = coors[bn*3+0] - coors[(bB*Nn+idx)*3+0];
    float dy = coors[bn*3+1] - coors[(bB*Nn+idx)*3+1];
    float dz = coors[bn*3+2] - coors[(bB*Nn+idx)*3+2];
    float x = dx*dx + dy*dy + dz*dz;
    float xs = x / (float)(1 << (s & 3));
    float sv = sinf(xs), cv = cosf(xs);
    float myre = (s < 4) ? sv : cv;
    float re[9];
    #pragma unroll
    for (int f = 0; f < 8; f++) re[f] = __shfl_sync(0xffffffffu, myre, f, 8);
    re[8] = x;

    float acc[4][16];
    #pragma unroll
    for (int h = 0; h < 4; h++)
        #pragma unroll
        for (int t = 0; t < 16; t++) acc[h][t] = 0.f;

    #pragma unroll 3
    for (int r = 0; r < 9; r++) {
        int i0 = (s + 8*r) * 4;
        float4 k4[4];
        #pragma unroll
        for (int h = 0; h < 4; h++)
            k4[h] = *(const float4*)&k1[krow + h*HP + i0];
        float4 r1v = make_float4(0.f, 0.f, 0.f, 0.f);
        #pragma unroll
        for (int f = 0; f < 9; f++) {
            float4 wv = *(float4*)&sWr[f*HP + i0];
            r1v.x += re[f]*wv.x; r1v.y += re[f]*wv.y;
            r1v.z += re[f]*wv.z; r1v.w += re[f]*wv.w;
        }
        float4 hv[4];
        #pragma unroll
        for (int h = 0; h < 4; h++) {
            float4 q4 = *(float4*)&sQ1[h*HP + i0];
            hv[h].x = fmaxf(q4.x + k4[h].x + r1v.x, 0.f);
            hv[h].y = fmaxf(q4.y + k4[h].y + r1v.y, 0.f);
            hv[h].z = fmaxf(q4.z + k4[h].z + r1v.z, 0.f);
            hv[h].w = fmaxf(q4.w + k4[h].w + r1v.w, 0.f);
        }
        #pragma unroll
        for (int t = 0; t < 16; t++) {
            float4 wv = *(float4*)&sW2t[t*W2S + i0];
            #pragma unroll
            for (int h = 0; h < 4; h++)
                acc[h][t] += hv[h].x*wv.x + hv[h].y*wv.y
                           + hv[h].z*wv.z + hv[h].w*wv.w;
        }
    }

    // butterfly reduce over 8-lane group
    #pragma unroll
    for (int h = 0; h < 4; h++)
        #pragma unroll
        for (int t = 0; t < 16; t++) {
            float v = acc[h][t];
            v += __shfl_xor_sync(0xffffffffu, v, 1);
            v += __shfl_xor_sync(0xffffffffu, v, 2);
            v += __shfl_xor_sync(0xffffffffu, v, 4);
            acc[h][t] = v;
        }

    // m -> smem (lanes s<4: h = s; row = j*4+h)
    if (s < 4) {
        float bsel[16];
        #pragma unroll
        for (int t = 0; t < 16; t++) {
            float v01 = (s & 1) ? acc[1][t] : acc[0][t];
            float v23 = (s & 1) ? acc[3][t] : acc[2][t];
            float v = (s & 2) ? v23 : v01;
            bsel[t] = fmaxf(v + sB2[t], 0.f);
        }
        int row = j*4 + s;
        #pragma unroll
        for (int tq = 0; tq < 4; tq++)
            *(float4*)&sM[row*16 + tq*4] =
                make_float4(bsel[tq*4], bsel[tq*4+1], bsel[tq*4+2], bsel[tq*4+3]);
    }
    __syncthreads();

    // blocked branch GEMM: thread = (row-quad rq, u-octet uo)
    {
        int rq = tid >> 3;           // j = rq (rows rq*4 .. rq*4+3 are h=0..3)
        int uo = tid & 7;
        float mvr[4][16];
        #pragma unroll
        for (int rr = 0; rr < 4; rr++)
            #pragma unroll
            for (int tq = 0; tq < 4; tq++) {
                float4 v = *(float4*)&sM[(rq*4+rr)*16 + tq*4];
                mvr[rr][tq*4+0] = v.x; mvr[rr][tq*4+1] = v.y;
                mvr[rr][tq*4+2] = v.z; mvr[rr][tq*4+3] = v.w;
            }
        #pragma unroll
        for (int br = 0; br < 2; br++) {
            const float* w1 = br ? sC1 : sA1;
            const float* w2 = br ? sC2 : sA2;
            const float* bb = br ? sBc : sBa;
            float4 bA = *(float4*)&bb[uo*8];
            float4 bBv = *(float4*)&bb[uo*8 + 4];
            float4 hA[4], hB[4];
            #pragma unroll
            for (int r = 0; r < 4; r++) { hA[r] = bA; hB[r] = bBv; }
            #pragma unroll
            for (int t = 0; t < 16; t++) {
                float4 wA = *(float4*)&w1[t*64 + uo*8];
                float4 wB = *(float4*)&w1[t*64 + uo*8 + 4];
                #pragma unroll
                for (int r = 0; r < 4; r++) {
                    float mval = mvr[r][t];
                    hA[r].x += mval*wA.x; hA[r].y += mval*wA.y;
                    hA[r].z += mval*wA.z; hA[r].w += mval*wA.w;
                    hB[r].x += mval*wB.x; hB[r].y += mval*wB.y;
                    hB[r].z += mval*wB.z; hB[r].w += mval*wB.w;
                }
            }
            float4 w2A = *(float4*)&w2[uo*8];
            float4 w2B = *(float4*)&w2[uo*8 + 4];
            float part[4];
            #pragma unroll
            for (int r = 0; r < 4; r++) {
                part[r] = fmaxf(hA[r].x,0.f)*w2A.x + fmaxf(hA[r].y,0.f)*w2A.y
                        + fmaxf(hA[r].z,0.f)*w2A.z + fmaxf(hA[r].w,0.f)*w2A.w
                        + fmaxf(hB[r].x,0.f)*w2B.x + fmaxf(hB[r].y,0.f)*w2B.y
                        + fmaxf(hB[r].z,0.f)*w2B.z + fmaxf(hB[r].w,0.f)*w2B.w;
            }
            #pragma unroll
            for (int r = 0; r < 4; r++) {
                part[r] += __shfl_xor_sync(0xffffffffu, part[r], 1);
                part[r] += __shfl_xor_sync(0xffffffffu, part[r], 2);
                part[r] += __shfl_xor_sync(0xffffffffu, part[r], 4);
            }
            if (uo == 0) {
                float* dst = br ? cwo : simo;
                float bias2 = sScal[br];
                #pragma unroll
                for (int r = 0; r < 4; r++) {
                    long e = ((long)(bB*Hh + r)*Nn + nn)*Jj + rq;
                    dst[e] = part[r] + bias2;
                }
            }
        }
    }
}

// ---------------- softmax over j, out = attn@v_nb, coors_out ----------------
__global__ void attend_kernel(const float* __restrict__ qkv,
                              const float* __restrict__ simi, const float* __restrict__ cwi,
                              const int* __restrict__ nbhd, const float* __restrict__ basis,
                              float* __restrict__ outh, float* __restrict__ coors_out)
{
    int bn = blockIdx.x;
    int b = bn / Nn, n = bn % Nn;
    int w = threadIdx.x >> 5, lane = threadIdx.x & 31;
    int idx = nbhd[bn*Jj + lane];

    float s = simi[((long)((b*Hh + w)*Nn + n))*Jj + lane];
    float mx = s;
    #pragma unroll
    for (int o = 16; o; o >>= 1) mx = fmaxf(mx, __shfl_xor_sync(0xffffffffu, mx, o));
    float e = expf(s - mx);
    float sum = e;
    #pragma unroll
    for (int o = 16; o; o >>= 1) sum += __shfl_xor_sync(0xffffffffu, sum, o);
    float attn = e / sum;

    float acc0 = 0.f, acc1 = 0.f;
    #pragma unroll
    for (int j = 0; j < Jj; j++) {
        float a = __shfl_sync(0xffffffffu, attn, j);
        int ij  = __shfl_sync(0xffffffffu, idx,  j);
        const float* vr = qkv + (long)(b*Nn + ij)*QKVC + 2*Hh*DHd + w*DHd;
        acc0 += a * vr[lane];
        acc1 += a * vr[lane + 32];
    }
    outh[(long)bn*Dd + w*DHd + lane]      = acc0;
    outh[(long)bn*Dd + w*DHd + lane + 32] = acc1;

    if (w == 0) {
        float cwt = 0.f;
        #pragma unroll
        for (int hh = 0; hh < Hh; hh++)
            cwt += cwi[((long)((b*Hh + hh)*Nn + n))*Jj + lane];
        const float* brow = basis + ((long)(b*Nn + n)*Nn + idx)*3;
        float cx = cwt*brow[0], cy = cwt*brow[1], cz = cwt*brow[2];
        #pragma unroll
        for (int o = 16; o; o >>= 1) {
            cx += __shfl_xor_sync(0xffffffffu, cx, o);
            cy += __shfl_xor_sync(0xffffffffu, cy, o);
            cz += __shfl_xor_sync(0xffffffffu, cz, o);
        }
        if (lane == 0) {
            coors_out[bn*3+0] = cx;
            coors_out[bn*3+1] = cy;
            coors_out[bn*3+2] = cz;
        }
    }
}

// ---------------- launch ----------------
extern "C" void kernel_launch(void* const* d_in, const int* in_sizes, int n_in,
                              void* d_out, int out_size)
{
    const float* feats  = (const float*)d_in[0];
    const float* coors  = (const float*)d_in[1];
    const float* basis  = (const float*)d_in[2];
    const int*   nbhd   = (const int*)  d_in[3];
    const float* w_qkv  = (const float*)d_in[4];
    const float* w_out  = (const float*)d_in[5];
    const float* b_out  = (const float*)d_in[6];
    const float* w_e1   = (const float*)d_in[7];
    const float* b_e1   = (const float*)d_in[8];
    const float* w_e2   = (const float*)d_in[9];
    const float* b_e2   = (const float*)d_in[10];
    const float* w_a1   = (const float*)d_in[11];
    const float* b_a1   = (const float*)d_in[12];
    const float* w_a2   = (const float*)d_in[13];
    const float* b_a2   = (const float*)d_in[14];
    const float* w_c1   = (const float*)d_in[15];
    const float* b_c1   = (const float*)d_in[16];
    const float* w_c2   = (const float*)d_in[17];
    const float* b_c2   = (const float*)d_in[18];

    float* out       = (float*)d_out;
    float* coors_out = out + (long)Bq*Nn*Dd;

    void* p;
    cudaGetSymbolAddress(&p, g_qkv);  float* qkv  = (float*)p;
    cudaGetSymbolAddress(&p, g_q1);   float* q1   = (float*)p;
    cudaGetSymbolAddress(&p, g_k1);   float* k1   = (float*)p;
    cudaGetSymbolAddress(&p, g_sim);  float* simv = (float*)p;
    cudaGetSymbolAddress(&p, g_cw);   float* cwv  = (float*)p;
    cudaGetSymbolAddress(&p, g_outh); float* outh = (float*)p;

    // 1) qkv = feats @ w_qkv
    gemm_tile<<<dim3(QKVC/64, (Bq*Nn)/64), 256>>>(feats, w_qkv, nullptr, qkv,
                                                  Bq*Nn, QKVC, Dd);

    // 2) q1/k1 tables (b_e1 folded into q1)
    const int smemQK = (64*HP*2 + 16*256*2) * 4;
    cudaFuncSetAttribute(qk1_kernel, cudaFuncAttributeMaxDynamicSharedMemorySize, smemQK);
    qk1_kernel<<<256, 256, smemQK>>>(qkv, w_e1, b_e1, q1, k1);

    // 2.5) alignment no-op so the ncu capture lands on edge_flat
    noop_kernel<<<1, 32>>>();

    // 3) edge_flat v4
    const int smemE = (9*HP + 16*W2S + 4*HP + 1024 + 1024 + 64*4 + 16 + 4 + 32 + 128*16) * 4;
    cudaFuncSetAttribute(edge_flat, cudaFuncAttributeMaxDynamicSharedMemorySize, smemE);
    edge_flat<<<NODES, 256, smemE>>>(q1, k1, coors, nbhd,
        w_e1, w_e2, b_e2, w_a1, b_a1, w_a2, b_a2, w_c1, b_c1, w_c2, b_c2,
        simv, cwv);

    // 4) softmax + v-gather + coors einsum
    attend_kernel<<<Bq*Nn, 128>>>(qkv, simv, cwv, nbhd, basis, outh, coors_out);

    // 5) out = outh @ w_out + b_out
    gemm_tile<<<dim3(Dd/64, (Bq*Nn)/64), 256>>>(outh, w_out, b_out, out,
                                                Bq*Nn, Dd, Dd);
}

// round 10
// speedup vs baseline: 2.2538x; 1.0681x over previous
#include <cuda_runtime.h>
#include <math.h>

#define Bq   2
#define Nn   2048
#define Dd   256
#define Hh   4
#define DHd  64
#define Jj   32
#define FFf  4
#define Mm   16
#define HID  274
#define HP   288            // padded hidden dim (cols 274..287 zero)
#define W2S  292            // sW2t row stride (floats)
#define QKVC (3*Hh*DHd)     // 768
#define NODES (Bq*Nn)       // 4096

// ---------------- scratch ----------------
__device__ float g_qkv [Bq*Nn*QKVC];
__device__ float g_q1  [Bq*Nn*Hh*HP];
__device__ float g_k1  [Bq*Nn*Hh*HP];
__device__ float g_sim [Bq*Hh*Nn*Jj];
__device__ float g_cw  [Bq*Hh*Nn*Jj];
__device__ float g_outh[Bq*Nn*Dd];

__global__ void noop_kernel() {}

// ---------------- gemm8x8: 128x128x32 double-buffered SGEMM, 8x8 micro ----------------
// Requires M%128==0, N%128... N%? grid covers N/GBN; here N in {256,768} with GBN=128.
#define GBM 128
#define GBN 128
#define GBK 32
#define GST (GBK*132)       // floats per stage per matrix

__global__ void __launch_bounds__(256, 2) gemm8x8(
    const float* __restrict__ A, const float* __restrict__ B,
    const float* __restrict__ bias, float* __restrict__ C,
    int M, int N, int K, int lda, int ldb, int ldc)
{
    extern __shared__ float gsm[];
    float* As = gsm;            // [2][GBK][132]
    float* Bs = gsm + 2*GST;    // [2][GBK][132]
    int tid = threadIdx.x;
    int tx = tid & 15, ty = tid >> 4;
    int rowBase = blockIdx.y * GBM;
    int colBase = blockIdx.x * GBN;

    int ar = tid >> 1;          // A staging row 0..127
    int ah = tid & 1;           // A staging k-half (ah*16)
    int bk = tid >> 3;          // B staging k 0..31
    int bq = tid & 7;           // B staging col base bq*16

    // stage 0 -> smem
    {
        const float* Ap = A + (long)(rowBase + ar) * lda + ah*16;
        #pragma unroll
        for (int q = 0; q < 4; q++) {
            float4 v = *(const float4*)(Ap + q*4);
            float* dst = As + (ah*16 + q*4)*132 + ar;
            dst[0] = v.x; dst[132] = v.y; dst[264] = v.z; dst[396] = v.w;
        }
        const float* Bp = B + (long)bk * ldb + colBase + bq*16;
        #pragma unroll
        for (int q = 0; q < 4; q++)
            *(float4*)(Bs + bk*132 + bq*16 + q*4) = *(const float4*)(Bp + q*4);
    }
    __syncthreads();

    float acc[8][8] = {};
    float4 pa[4], pb[4];
    int nkb = K / GBK;
    for (int kb = 0; kb < nkb; kb++) {
        int cur = kb & 1;
        if (kb + 1 < nkb) {
            const float* Ap = A + (long)(rowBase + ar)*lda + (kb+1)*GBK + ah*16;
            #pragma unroll
            for (int q = 0; q < 4; q++) pa[q] = *(const float4*)(Ap + q*4);
            const float* Bp = B + (long)((kb+1)*GBK + bk)*ldb + colBase + bq*16;
            #pragma unroll
            for (int q = 0; q < 4; q++) pb[q] = *(const float4*)(Bp + q*4);
        }
        const float* Ac = As + cur*GST;
        const float* Bc = Bs + cur*GST;
        #pragma unroll
        for (int kk = 0; kk < GBK; kk++) {
            float4 a0 = *(const float4*)(Ac + kk*132 + ty*8);
            float4 a1 = *(const float4*)(Ac + kk*132 + ty*8 + 4);
            float4 b0 = *(const float4*)(Bc + kk*132 + tx*8);
            float4 b1 = *(const float4*)(Bc + kk*132 + tx*8 + 4);
            float av0=a0.x, av1=a0.y, av2=a0.z, av3=a0.w;
            float av4=a1.x, av5=a1.y, av6=a1.z, av7=a1.w;
            float bv0=b0.x, bv1=b0.y, bv2=b0.z, bv3=b0.w;
            float bv4=b1.x, bv5=b1.y, bv6=b1.z, bv7=b1.w;
            #define ROW(r, avr) \
                acc[r][0]+=avr*bv0; acc[r][1]+=avr*bv1; acc[r][2]+=avr*bv2; acc[r][3]+=avr*bv3; \
                acc[r][4]+=avr*bv4; acc[r][5]+=avr*bv5; acc[r][6]+=avr*bv6; acc[r][7]+=avr*bv7;
            ROW(0, av0) ROW(1, av1) ROW(2, av2) ROW(3, av3)
            ROW(4, av4) ROW(5, av5) ROW(6, av6) ROW(7, av7)
            #undef ROW
        }
        if (kb + 1 < nkb) {
            int nxt = cur ^ 1;
            #pragma unroll
            for (int q = 0; q < 4; q++) {
                float* dst = As + nxt*GST + (ah*16 + q*4)*132 + ar;
                dst[0] = pa[q].x; dst[132] = pa[q].y; dst[264] = pa[q].z; dst[396] = pa[q].w;
            }
            #pragma unroll
            for (int q = 0; q < 4; q++)
                *(float4*)(Bs + nxt*GST + bk*132 + bq*16 + q*4) = pb[q];
        }
        __syncthreads();
    }

    #pragma unroll
    for (int r = 0; r < 8; r++) {
        long row = rowBase + ty*8 + r;
        float* Crow = C + row*ldc + colBase + tx*8;
        #pragma unroll
        for (int c2 = 0; c2 < 2; c2++) {
            float4 v;
            v.x = acc[r][c2*4+0]; v.y = acc[r][c2*4+1];
            v.z = acc[r][c2*4+2]; v.w = acc[r][c2*4+3];
            if (bias) {
                const float* bp = bias + colBase + tx*8 + c2*4;
                v.x += bp[0]; v.y += bp[1]; v.z += bp[2]; v.w += bp[3];
            }
            *(float4*)(Crow + c2*4) = v;
        }
    }
}

// ---------------- q1/k1 precompute; 32 nodes/block; b_e1 folded into q1 ----------------
__global__ void __launch_bounds__(256,1) qk1_kernel(
    const float* __restrict__ qkv, const float* __restrict__ w_e1,
    const float* __restrict__ b_e1,
    float* __restrict__ q1, float* __restrict__ k1)
{
    extern __shared__ float sm[];
    float* sWq = sm;             // [64][HP]
    float* sWk = sWq + 64*HP;    // [64][HP]
    float* sAq = sWk + 64*HP;    // [16][256]
    float* sAk = sAq + 16*256;   // [16][256]
    int tid = threadIdx.x;

    for (int i = tid; i < 64*HP; i += 256) {
        int r = i / HP, o = i - r*HP;
        sWq[i] = (o < HID) ? w_e1[r*HID + o] : 0.f;
        sWk[i] = (o < HID) ? w_e1[(64 + r)*HID + o] : 0.f;
    }

    int ty = tid >> 4, tx = tid & 15;

    for (int chunk = 0; chunk < 2; chunk++) {
        int node0 = blockIdx.x * 32 + chunk * 16;
        __syncthreads();   // protects W staging (c0) / prev-chunk reads (c1)
        for (int i = tid; i < 1024; i += 256) {
            int t = i >> 6, cq = i & 63;
            *(float4*)&sAq[t*256 + cq*4] =
                *(const float4*)&qkv[(long)(node0 + t)*QKVC + cq*4];
            *(float4*)&sAk[t*256 + cq*4] =
                *(const float4*)&qkv[(long)(node0 + t)*QKVC + 256 + cq*4];
        }
        __syncthreads();

        for (int pass = 0; pass < 2; pass++) {
            const float* A = pass ? sAk : sAq;
            const float* W = pass ? sWk : sWq;
            float* Cg = pass ? k1 : q1;
            float acc[4][18];
            #pragma unroll
            for (int r = 0; r < 4; r++)
                #pragma unroll
                for (int c = 0; c < 18; c++) acc[r][c] = 0.f;
            #pragma unroll 4
            for (int i = 0; i < 64; i++) {
                float a[4];
                #pragma unroll
                for (int r = 0; r < 4; r++) a[r] = A[ty*256 + r*64 + i];
                #pragma unroll
                for (int c = 0; c < 18; c++) {
                    float w = W[i*HP + tx + 16*c];
                    #pragma unroll
                    for (int r = 0; r < 4; r++) acc[r][c] += a[r] * w;
                }
            }
            #pragma unroll
            for (int r = 0; r < 4; r++) {
                long grow = (long)(node0 + ty)*4 + r;
                #pragma unroll
                for (int c = 0; c < 18; c++) {
                    int o = tx + 16*c;
                    float bz = (pass == 0 && o < HID) ? b_e1[o] : 0.f;
                    Cg[grow*HP + o] = acc[r][c] + bz;
                }
            }
        }
    }
}

// ---------------- edge_flat v4: v2 main loop + smem-m blocked branch GEMM ----------------
__global__ void __launch_bounds__(256, 2) edge_flat(
    const float* __restrict__ q1, const float* __restrict__ k1,
    const float* __restrict__ coors, const int* __restrict__ nbhd,
    const float* __restrict__ w_e1,
    const float* __restrict__ w_e2, const float* __restrict__ b_e2,
    const float* __restrict__ w_a1, const float* __restrict__ b_a1,
    const float* __restrict__ w_a2, const float* __restrict__ b_a2,
    const float* __restrict__ w_c1, const float* __restrict__ b_c1,
    const float* __restrict__ w_c2, const float* __restrict__ b_c2,
    float* __restrict__ simo, float* __restrict__ cwo)
{
    extern __shared__ float sm[];
    float* sWr  = sm;               // [9][HP]
    float* sW2t = sWr + 9*HP;       // [16][W2S]  (transposed w_e2)
    float* sQ1  = sW2t + 16*W2S;    // [4][HP]  (q1 row incl. b1)
    float* sA1  = sQ1 + 4*HP;       // [16][64]
    float* sC1  = sA1 + 1024;       // [16][64]
    float* sBa  = sC1 + 1024;       // [64]
    float* sBc  = sBa + 64;         // [64]
    float* sA2  = sBc + 64;         // [64]
    float* sC2  = sA2 + 64;         // [64]
    float* sB2  = sC2 + 64;         // [16]
    float* sScal= sB2 + 16;         // [4]
    int*   sIdx = (int*)(sScal + 4);// [32]
    float* sM   = (float*)(sIdx + 32); // [128][16]  m values (row = j*4+h)

    int tid = threadIdx.x;
    int bn  = blockIdx.x;
    int bB  = bn >> 11;
    int nn  = bn & (Nn - 1);

    for (int i = tid; i < 9*HP; i += 256) {
        int f = i / HP, o = i - f*HP;
        sWr[i] = (o < HID) ? w_e1[(128 + f)*HID + o] : 0.f;
    }
    for (int i = tid; i < 16*(W2S - HID); i += 256) {
        int t = i / (W2S - HID), o = HID + i % (W2S - HID);
        sW2t[t*W2S + o] = 0.f;
    }
    for (int i = tid; i < HID*4; i += 256) {          // i-row, t-quad
        int irow = i >> 2, tq = i & 3;
        float4 v = *(const float4*)&w_e2[irow*16 + tq*4];
        sW2t[(tq*4+0)*W2S + irow] = v.x;
        sW2t[(tq*4+1)*W2S + irow] = v.y;
        sW2t[(tq*4+2)*W2S + irow] = v.z;
        sW2t[(tq*4+3)*W2S + irow] = v.w;
    }
    for (int i = tid; i < (4*HP)/4; i += 256)
        ((float4*)sQ1)[i] = ((const float4*)(q1 + (long)bn*4*HP))[i];
    if (tid < 256) {
        ((float4*)sA1)[tid] = ((const float4*)w_a1)[tid];
        ((float4*)sC1)[tid] = ((const float4*)w_c1)[tid];
    }
    if (tid < 16) {
        ((float4*)sBa)[tid] = ((const float4*)b_a1)[tid];
        ((float4*)sBc)[tid] = ((const float4*)b_c1)[tid];
        ((float4*)sA2)[tid] = ((const float4*)w_a2)[tid];
        ((float4*)sC2)[tid] = ((const float4*)w_c2)[tid];
    }
    if (tid < 16) sB2[tid] = b_e2[tid];
    if (tid == 0) { sScal[0] = b_a2[0]; sScal[1] = b_c2[0]; }
    if (tid < 32) sIdx[tid] = nbhd[bn*Jj + tid];
    __syncthreads();

    int w = tid >> 5, lane = tid & 31;
    int qq = lane >> 3, s = lane & 7;
    int j = w*4 + qq;
    int idx = sIdx[j];
    long krow = ((long)(bB*Nn + idx)*4) * HP;

    // rel_enc: lanes s=0..3 -> sin(x/2^s), s=4..7 -> cos(x/2^(s-4))
    float dx = coors[bn*3+0] - coors[(bB*Nn+idx)*3+0];
    float dy = coors[bn*3+1] - coors[(bB*Nn+idx)*3+1];
    float dz = coors[bn*3+2] - coors[(bB*Nn+idx)*3+2];
    float x = dx*dx + dy*dy + dz*dz;
    float xs = x / (float)(1 << (s & 3));
    float sv = sinf(xs), cv = cosf(xs);
    float myre = (s < 4) ? sv : cv;
    float re[9];
    #pragma unroll
    for (int f = 0; f < 8; f++) re[f] = __shfl_sync(0xffffffffu, myre, f, 8);
    re[8] = x;

    float acc[4][16];
    #pragma unroll
    for (int h = 0; h < 4; h++)
        #pragma unroll
        for (int t = 0; t < 16; t++) acc[h][t] = 0.f;

    #pragma unroll 3
    for (int r = 0; r < 9; r++) {
        int i0 = (s + 8*r) * 4;
        float4 k4[4];
        #pragma unroll
        for (int h = 0; h < 4; h++)
            k4[h] = *(const float4*)&k1[krow + h*HP + i0];
        float4 r1v = make_float4(0.f, 0.f, 0.f, 0.f);
        #pragma unroll
        for (int f = 0; f < 9; f++) {
            float4 wv = *(float4*)&sWr[f*HP + i0];
            r1v.x += re[f]*wv.x; r1v.y += re[f]*wv.y;
            r1v.z += re[f]*wv.z; r1v.w += re[f]*wv.w;
        }
        float4 hv[4];
        #pragma unroll
        for (int h = 0; h < 4; h++) {
            float4 q4 = *(float4*)&sQ1[h*HP + i0];
            hv[h].x = fmaxf(q4.x + k4[h].x + r1v.x, 0.f);
            hv[h].y = fmaxf(q4.y + k4[h].y + r1v.y, 0.f);
            hv[h].z = fmaxf(q4.z + k4[h].z + r1v.z, 0.f);
            hv[h].w = fmaxf(q4.w + k4[h].w + r1v.w, 0.f);
        }
        #pragma unroll
        for (int t = 0; t < 16; t++) {
            float4 wv = *(float4*)&sW2t[t*W2S + i0];
            #pragma unroll
            for (int h = 0; h < 4; h++)
                acc[h][t] += hv[h].x*wv.x + hv[h].y*wv.y
                           + hv[h].z*wv.z + hv[h].w*wv.w;
        }
    }

    // butterfly reduce over 8-lane group
    #pragma unroll
    for (int h = 0; h < 4; h++)
        #pragma unroll
        for (int t = 0; t < 16; t++) {
            float v = acc[h][t];
            v += __shfl_xor_sync(0xffffffffu, v, 1);
            v += __shfl_xor_sync(0xffffffffu, v, 2);
            v += __shfl_xor_sync(0xffffffffu, v, 4);
            acc[h][t] = v;
        }

    // m -> smem (lanes s<4: h = s; row = j*4+h)
    if (s < 4) {
        float bsel[16];
        #pragma unroll
        for (int t = 0; t < 16; t++) {
            float v01 = (s & 1) ? acc[1][t] : acc[0][t];
            float v23 = (s & 1) ? acc[3][t] : acc[2][t];
            float v = (s & 2) ? v23 : v01;
            bsel[t] = fmaxf(v + sB2[t], 0.f);
        }
        int row = j*4 + s;
        #pragma unroll
        for (int tq = 0; tq < 4; tq++)
            *(float4*)&sM[row*16 + tq*4] =
                make_float4(bsel[tq*4], bsel[tq*4+1], bsel[tq*4+2], bsel[tq*4+3]);
    }
    __syncthreads();

    // blocked branch GEMM: thread = (row-quad rq, u-octet uo)
    {
        int rq = tid >> 3;           // j = rq (rows rq*4 .. rq*4+3 are h=0..3)
        int uo = tid & 7;
        float mvr[4][16];
        #pragma unroll
        for (int rr = 0; rr < 4; rr++)
            #pragma unroll
            for (int tq = 0; tq < 4; tq++) {
                float4 v = *(float4*)&sM[(rq*4+rr)*16 + tq*4];
                mvr[rr][tq*4+0] = v.x; mvr[rr][tq*4+1] = v.y;
                mvr[rr][tq*4+2] = v.z; mvr[rr][tq*4+3] = v.w;
            }
        #pragma unroll
        for (int br = 0; br < 2; br++) {
            const float* w1 = br ? sC1 : sA1;
            const float* w2 = br ? sC2 : sA2;
            const float* bb = br ? sBc : sBa;
            float4 bA = *(float4*)&bb[uo*8];
            float4 bBv = *(float4*)&bb[uo*8 + 4];
            float4 hA[4], hB[4];
            #pragma unroll
            for (int r = 0; r < 4; r++) { hA[r] = bA; hB[r] = bBv; }
            #pragma unroll
            for (int t = 0; t < 16; t++) {
                float4 wA = *(float4*)&w1[t*64 + uo*8];
                float4 wB = *(float4*)&w1[t*64 + uo*8 + 4];
                #pragma unroll
                for (int r = 0; r < 4; r++) {
                    float mval = mvr[r][t];
                    hA[r].x += mval*wA.x; hA[r].y += mval*wA.y;
                    hA[r].z += mval*wA.z; hA[r].w += mval*wA.w;
                    hB[r].x += mval*wB.x; hB[r].y += mval*wB.y;
                    hB[r].z += mval*wB.z; hB[r].w += mval*wB.w;
                }
            }
            float4 w2A = *(float4*)&w2[uo*8];
            float4 w2B = *(float4*)&w2[uo*8 + 4];
            float part[4];
            #pragma unroll
            for (int r = 0; r < 4; r++) {
                part[r] = fmaxf(hA[r].x,0.f)*w2A.x + fmaxf(hA[r].y,0.f)*w2A.y
                        + fmaxf(hA[r].z,0.f)*w2A.z + fmaxf(hA[r].w,0.f)*w2A.w
                        + fmaxf(hB[r].x,0.f)*w2B.x + fmaxf(hB[r].y,0.f)*w2B.y
                        + fmaxf(hB[r].z,0.f)*w2B.z + fmaxf(hB[r].w,0.f)*w2B.w;
            }
            #pragma unroll
            for (int r = 0; r < 4; r++) {
                part[r] += __shfl_xor_sync(0xffffffffu, part[r], 1);
                part[r] += __shfl_xor_sync(0xffffffffu, part[r], 2);
                part[r] += __shfl_xor_sync(0xffffffffu, part[r], 4);
            }
            if (uo == 0) {
                float* dst = br ? cwo : simo;
                float bias2 = sScal[br];
                #pragma unroll
                for (int r = 0; r < 4; r++) {
                    long e = ((long)(bB*Hh + r)*Nn + nn)*Jj + rq;
                    dst[e] = part[r] + bias2;
                }
            }
        }
    }
}

// ---------------- softmax over j, out = attn@v_nb, coors_out ----------------
__global__ void attend_kernel(const float* __restrict__ qkv,
                              const float* __restrict__ simi, const float* __restrict__ cwi,
                              const int* __restrict__ nbhd, const float* __restrict__ basis,
                              float* __restrict__ outh, float* __restrict__ coors_out)
{
    int bn = blockIdx.x;
    int b = bn / Nn, n = bn % Nn;
    int w = threadIdx.x >> 5, lane = threadIdx.x & 31;
    int idx = nbhd[bn*Jj + lane];

    float s = simi[((long)((b*Hh + w)*Nn + n))*Jj + lane];
    float mx = s;
    #pragma unroll
    for (int o = 16; o; o >>= 1) mx = fmaxf(mx, __shfl_xor_sync(0xffffffffu, mx, o));
    float e = expf(s - mx);
    float sum = e;
    #pragma unroll
    for (int o = 16; o; o >>= 1) sum += __shfl_xor_sync(0xffffffffu, sum, o);
    float attn = e / sum;

    float acc0 = 0.f, acc1 = 0.f;
    #pragma unroll
    for (int j = 0; j < Jj; j++) {
        float a = __shfl_sync(0xffffffffu, attn, j);
        int ij  = __shfl_sync(0xffffffffu, idx,  j);
        const float* vr = qkv + (long)(b*Nn + ij)*QKVC + 2*Hh*DHd + w*DHd;
        acc0 += a * vr[lane];
        acc1 += a * vr[lane + 32];
    }
    outh[(long)bn*Dd + w*DHd + lane]      = acc0;
    outh[(long)bn*Dd + w*DHd + lane + 32] = acc1;

    if (w == 0) {
        float cwt = 0.f;
        #pragma unroll
        for (int hh = 0; hh < Hh; hh++)
            cwt += cwi[((long)((b*Hh + hh)*Nn + n))*Jj + lane];
        const float* brow = basis + ((long)(b*Nn + n)*Nn + idx)*3;
        float cx = cwt*brow[0], cy = cwt*brow[1], cz = cwt*brow[2];
        #pragma unroll
        for (int o = 16; o; o >>= 1) {
            cx += __shfl_xor_sync(0xffffffffu, cx, o);
            cy += __shfl_xor_sync(0xffffffffu, cy, o);
            cz += __shfl_xor_sync(0xffffffffu, cz, o);
        }
        if (lane == 0) {
            coors_out[bn*3+0] = cx;
            coors_out[bn*3+1] = cy;
            coors_out[bn*3+2] = cz;
        }
    }
}

// ---------------- launch ----------------
extern "C" void kernel_launch(void* const* d_in, const int* in_sizes, int n_in,
                              void* d_out, int out_size)
{
    const float* feats  = (const float*)d_in[0];
    const float* coors  = (const float*)d_in[1];
    const float* basis  = (const float*)d_in[2];
    const int*   nbhd   = (const int*)  d_in[3];
    const float* w_qkv  = (const float*)d_in[4];
    const float* w_out  = (const float*)d_in[5];
    const float* b_out  = (const float*)d_in[6];
    const float* w_e1   = (const float*)d_in[7];
    const float* b_e1   = (const float*)d_in[8];
    const float* w_e2   = (const float*)d_in[9];
    const float* b_e2   = (const float*)d_in[10];
    const float* w_a1   = (const float*)d_in[11];
    const float* b_a1   = (const float*)d_in[12];
    const float* w_a2   = (const float*)d_in[13];
    const float* b_a2   = (const float*)d_in[14];
    const float* w_c1   = (const float*)d_in[15];
    const float* b_c1   = (const float*)d_in[16];
    const float* w_c2   = (const float*)d_in[17];
    const float* b_c2   = (const float*)d_in[18];

    float* out       = (float*)d_out;
    float* coors_out = out + (long)Bq*Nn*Dd;

    void* p;
    cudaGetSymbolAddress(&p, g_qkv);  float* qkv  = (float*)p;
    cudaGetSymbolAddress(&p, g_q1);   float* q1   = (float*)p;
    cudaGetSymbolAddress(&p, g_k1);   float* k1   = (float*)p;
    cudaGetSymbolAddress(&p, g_sim);  float* simv = (float*)p;
    cudaGetSymbolAddress(&p, g_cw);   float* cwv  = (float*)p;
    cudaGetSymbolAddress(&p, g_outh); float* outh = (float*)p;

    const int smemG = 4 * GST * 4;   // 2 stages x (A,B) x GST floats
    cudaFuncSetAttribute(gemm8x8, cudaFuncAttributeMaxDynamicSharedMemorySize, smemG);

    // 1) qkv = feats @ w_qkv : (4096x768), K=256
    gemm8x8<<<dim3(QKVC/GBN, (Bq*Nn)/GBM), 256, smemG>>>(
        feats, w_qkv, nullptr, qkv, Bq*Nn, QKVC, Dd, Dd, QKVC, QKVC);

    // 2) q1/k1 tables (b_e1 folded into q1), 32 nodes/block
    const int smemQK = (64*HP*2 + 16*256*2) * 4;
    cudaFuncSetAttribute(qk1_kernel, cudaFuncAttributeMaxDynamicSharedMemorySize, smemQK);
    qk1_kernel<<<NODES/32, 256, smemQK>>>(qkv, w_e1, b_e1, q1, k1);

    // 2.5) alignment no-op so the ncu capture lands on edge_flat
    noop_kernel<<<1, 32>>>();

    // 3) edge_flat v4
    const int smemE = (9*HP + 16*W2S + 4*HP + 1024 + 1024 + 64*4 + 16 + 4 + 32 + 128*16) * 4;
    cudaFuncSetAttribute(edge_flat, cudaFuncAttributeMaxDynamicSharedMemorySize, smemE);
    edge_flat<<<NODES, 256, smemE>>>(q1, k1, coors, nbhd,
        w_e1, w_e2, b_e2, w_a1, b_a1, w_a2, b_a2, w_c1, b_c1, w_c2, b_c2,
        simv, cwv);

    // 4) softmax + v-gather + coors einsum
    attend_kernel<<<Bq*Nn, 128>>>(qkv, simv, cwv, nbhd, basis, outh, coors_out);

    // 5) out = outh @ w_out + b_out : (4096x256), K=256
    gemm8x8<<<dim3(Dd/GBN, (Bq*Nn)/GBM), 256, smemG>>>(
        outh, w_out, b_out, out, Bq*Nn, Dd, Dd, Dd, Dd, Dd);
}